// round 8
// baseline (speedup 1.0000x reference)
#include <cuda_runtime.h>
#include <cuda_bf16.h>
#include <cstdint>

// ============================ problem constants ============================
#define BB   64
#define LL   12
#define NN   883
#define DD   64
#define TT   12
#define MM   64
#define ROWS (BB*NN)            // 56512 = 883 * 64 exactly -> grid 883, no tail

// ============================ scratch ======================================
// Pre-swizzled B fragments for mma.m16n8k16 (row.col), lane-indexed:
//   index = (((t*2 + v)*8 + j)*4 + kk)*32 + lane   (v: 0=hi split, 1=lo split)
//   .x = pack(e_k, e_k+1), .y = pack(e_k+8, e_k+9)  for n = 8j + lane/4, k = 16kk + 2*(lane%4)
// GEMM1: B[k=d][n=m] = M[t][m][d]   GEMM2: B[k=m][n=d] = M[t][m][d]
__device__ uint2 g_Bf1[TT * 2 * 8 * 4 * 32];
__device__ uint2 g_Bf2[TT * 2 * 8 * 4 * 32];

// ============================ helpers ======================================
__device__ __forceinline__ uint32_t pack_bf16(__nv_bfloat16 lo, __nv_bfloat16 hi) {
    return (uint32_t)__bfloat16_as_ushort(lo) | ((uint32_t)__bfloat16_as_ushort(hi) << 16);
}
__device__ __forceinline__ void split_bf16(float v, __nv_bfloat16& h, __nv_bfloat16& l) {
    h = __float2bfloat16_rn(v);
    l = __float2bfloat16_rn(v - __bfloat162float(h));
}
// D += A * B  (m16n8k16, bf16 in, fp32 accum)
__device__ __forceinline__ void mma_bf16(float* c, const uint32_t* a,
                                         uint32_t b0, uint32_t b1) {
    asm volatile(
        "mma.sync.aligned.m16n8k16.row.col.f32.bf16.bf16.f32 "
        "{%0,%1,%2,%3}, {%4,%5,%6,%7}, {%8,%9}, {%0,%1,%2,%3};"
        : "+f"(c[0]), "+f"(c[1]), "+f"(c[2]), "+f"(c[3])
        : "r"(a[0]), "r"(a[1]), "r"(a[2]), "r"(a[3]), "r"(b0), "r"(b1));
}

// ================= kernel 1: build lane-indexed B fragment tables ==========
__global__ __launch_bounds__(256) void ma_tables(const float* __restrict__ Mw) {
    // one thread per uint2 fragment word: 12t * 2g * 2v * 8j * 4kk * 32lane = 49152
    int i = blockIdx.x * 256 + threadIdx.x;
    int lane =  i        & 31;
    int kk   = (i >> 5)  & 3;
    int j    = (i >> 7)  & 7;
    int v    = (i >> 10) & 1;
    int g    = (i >> 11) & 1;
    int t    =  i >> 12;
    int nidx = 8 * j + (lane >> 2);
    int kbase = 16 * kk + 2 * (lane & 3);
    const float* Mt = Mw + t * (MM * DD);
    float e0, e1, e2, e3;
    if (g == 0) {   // GEMM1: B[k=d][n=m] = M[m][d]
        int m = nidx;
        e0 = Mt[m * DD + kbase];
        e1 = Mt[m * DD + kbase + 1];
        e2 = Mt[m * DD + kbase + 8];
        e3 = Mt[m * DD + kbase + 9];
    } else {        // GEMM2: B[k=m][n=d] = M[m][d]
        int d = nidx;
        e0 = Mt[(kbase    ) * DD + d];
        e1 = Mt[(kbase + 1) * DD + d];
        e2 = Mt[(kbase + 8) * DD + d];
        e3 = Mt[(kbase + 9) * DD + d];
    }
    __nv_bfloat16 h, l, f0, f1, f2, f3;
    split_bf16(e0, h, l); f0 = v ? l : h;
    split_bf16(e1, h, l); f1 = v ? l : h;
    split_bf16(e2, h, l); f2 = v ? l : h;
    split_bf16(e3, h, l); f3 = v ? l : h;
    uint2 w = make_uint2(pack_bf16(f0, f1), pack_bf16(f2, f3));
    int idx = (((t * 2 + v) * 8 + j) * 4 + kk) * 32 + lane;
    if (g == 0) g_Bf1[idx] = w; else g_Bf2[idx] = w;
}

// ============ kernel 2: fused reduce + GEMM-softmax-GEMM (HMMA) ============
// 128 threads = 4 warps; warp w owns rows [blk*64 + 16w, +16). 883 blocks, no tail.
#define SH_STRIDE 33   // padded row stride (u32 words) to avoid LDS bank conflicts

__global__ __launch_bounds__(128, 5) void ma_main(const float* __restrict__ x,
                                                  float* __restrict__ out) {
    __shared__ uint32_t sh_hi[64 * SH_STRIDE];
    __shared__ uint32_t sh_lo[64 * SH_STRIDE];

    int tid  = threadIdx.x;
    int wid  = tid >> 5;
    int lane = tid & 31;
    int qr   = lane >> 2;        // fragment row within tile (0..7)
    int qc   = lane & 3;         // k/col group (0..3)

    // ---- phase 0: reduce x over L, split to bf16 hi/lo in smem ----
    {
        int rl   = tid >> 1;         // local row 0..63
        int half = tid & 1;          // d-half
        int row  = blockIdx.x * 64 + rl;
        int b = row / NN;
        int n = row - b * NN;
        const float* bp = x + ((size_t)b * LL * NN + n) * DD + half * 32;
        float4 av[8];
#pragma unroll
        for (int i = 0; i < 8; i++) av[i] = reinterpret_cast<const float4*>(bp)[i];
#pragma unroll
        for (int l = 1; l < LL; l++) {
            const float4* p = reinterpret_cast<const float4*>(bp + (size_t)l * NN * DD);
#pragma unroll
            for (int i = 0; i < 8; i++) {
                float4 v = p[i];
                av[i].x += v.x; av[i].y += v.y; av[i].z += v.z; av[i].w += v.w;
            }
        }
        int bs = rl * SH_STRIDE + half * 16;
#pragma unroll
        for (int i = 0; i < 8; i++) {
            __nv_bfloat16 hx,lx,hy,ly,hz,lz,hw,lw;
            split_bf16(av[i].x, hx, lx); split_bf16(av[i].y, hy, ly);
            split_bf16(av[i].z, hz, lz); split_bf16(av[i].w, hw, lw);
            sh_hi[bs + 2*i]     = pack_bf16(hx, hy);
            sh_hi[bs + 2*i + 1] = pack_bf16(hz, hw);
            sh_lo[bs + 2*i]     = pack_bf16(lx, ly);
            sh_lo[bs + 2*i + 1] = pack_bf16(lz, lw);
        }
    }
    __syncthreads();

    // ---- persistent A-hi fragments + output pointers ----
    int lA = wid * 16 + qr;          // local rows of this lane's fragments
    int lB = lA + 8;
    int rA = blockIdx.x * 64 + lA;
    int rB = rA + 8;
    int bA = rA / NN, nA = rA - bA * NN;
    int bB = rB / NN, nB = rB - bB * NN;
    float* outA = out + ((size_t)bA * TT * NN + nA) * DD + 2 * qc;
    float* outB = out + ((size_t)bB * TT * NN + nB) * DD + 2 * qc;

    uint32_t ah[16];
#pragma unroll
    for (int kk = 0; kk < 4; kk++) {
        int o = 8 * kk + qc;
        ah[4*kk+0] = sh_hi[lA * SH_STRIDE + o];
        ah[4*kk+1] = sh_hi[lB * SH_STRIDE + o];
        ah[4*kk+2] = sh_hi[lA * SH_STRIDE + o + 4];
        ah[4*kk+3] = sh_hi[lB * SH_STRIDE + o + 4];
    }

    const uint2* B1 = g_Bf1 + lane;
    const uint2* B2 = g_Bf2 + lane;

#pragma unroll 1
    for (int t = 0; t < TT; t++) {
        const uint2* B1h = B1 + (size_t)(t * 2    ) * 1024;
        const uint2* B1l = B1 + (size_t)(t * 2 + 1) * 1024;
        const uint2* B2h = B2 + (size_t)(t * 2    ) * 1024;
        const uint2* B2l = B2 + (size_t)(t * 2 + 1) * 1024;

        // ---- GEMM1: scores = xs @ M^T (3-term split, B loaded once) ----
        float acc[32];
#pragma unroll
        for (int i = 0; i < 32; i++) acc[i] = 0.f;
#pragma unroll
        for (int kk = 0; kk < 4; kk++) {
            int o = 8 * kk + qc;
            uint32_t alk[4];
            alk[0] = sh_lo[lA * SH_STRIDE + o];
            alk[1] = sh_lo[lB * SH_STRIDE + o];
            alk[2] = sh_lo[lA * SH_STRIDE + o + 4];
            alk[3] = sh_lo[lB * SH_STRIDE + o + 4];
#pragma unroll
            for (int j = 0; j < 8; j++) {
                uint2 bh = B1h[(j * 4 + kk) * 32];
                uint2 bl = B1l[(j * 4 + kk) * 32];
                mma_bf16(&acc[4*j], ah + 4*kk, bh.x, bh.y);
                mma_bf16(&acc[4*j], alk,       bh.x, bh.y);
                mma_bf16(&acc[4*j], ah + 4*kk, bl.x, bl.y);
            }
        }

        // ---- softmax over 64 m (rows A/B split across 4-lane quads) ----
        float mA = -1e30f, mB = -1e30f;
#pragma unroll
        for (int j = 0; j < 8; j++) {
            mA = fmaxf(mA, fmaxf(acc[4*j],   acc[4*j+1]));
            mB = fmaxf(mB, fmaxf(acc[4*j+2], acc[4*j+3]));
        }
        mA = fmaxf(mA, __shfl_xor_sync(0xffffffffu, mA, 1));
        mA = fmaxf(mA, __shfl_xor_sync(0xffffffffu, mA, 2));
        mB = fmaxf(mB, __shfl_xor_sync(0xffffffffu, mB, 1));
        mB = fmaxf(mB, __shfl_xor_sync(0xffffffffu, mB, 2));
        float sA = 0.f, sB = 0.f;
#pragma unroll
        for (int j = 0; j < 8; j++) {
            acc[4*j]   = __expf(acc[4*j]   - mA);
            acc[4*j+1] = __expf(acc[4*j+1] - mA);
            acc[4*j+2] = __expf(acc[4*j+2] - mB);
            acc[4*j+3] = __expf(acc[4*j+3] - mB);
            sA += acc[4*j] + acc[4*j+1];
            sB += acc[4*j+2] + acc[4*j+3];
        }
        sA += __shfl_xor_sync(0xffffffffu, sA, 1);
        sA += __shfl_xor_sync(0xffffffffu, sA, 2);
        sB += __shfl_xor_sync(0xffffffffu, sB, 1);
        sB += __shfl_xor_sync(0xffffffffu, sB, 2);
        float iA = 1.0f / sA, iB = 1.0f / sB;

        // ---- GEMM2: value = p @ M (p split on the fly per kk) ----
        float outv[32];
#pragma unroll
        for (int i = 0; i < 32; i++) outv[i] = 0.f;
#pragma unroll
        for (int kk = 0; kk < 4; kk++) {
            int j0 = 2 * kk, j1 = 2 * kk + 1;
            float p00 = acc[4*j0]   * iA, p01 = acc[4*j0+1] * iA;
            float p02 = acc[4*j0+2] * iB, p03 = acc[4*j0+3] * iB;
            float p10 = acc[4*j1]   * iA, p11 = acc[4*j1+1] * iA;
            float p12 = acc[4*j1+2] * iB, p13 = acc[4*j1+3] * iB;
            uint32_t a_h[4], a_l[4];
            __nv_bfloat16 h0,l0,h1,l1;
            split_bf16(p00, h0, l0); split_bf16(p01, h1, l1);
            a_h[0] = pack_bf16(h0, h1); a_l[0] = pack_bf16(l0, l1);
            split_bf16(p02, h0, l0); split_bf16(p03, h1, l1);
            a_h[1] = pack_bf16(h0, h1); a_l[1] = pack_bf16(l0, l1);
            split_bf16(p10, h0, l0); split_bf16(p11, h1, l1);
            a_h[2] = pack_bf16(h0, h1); a_l[2] = pack_bf16(l0, l1);
            split_bf16(p12, h0, l0); split_bf16(p13, h1, l1);
            a_h[3] = pack_bf16(h0, h1); a_l[3] = pack_bf16(l0, l1);
#pragma unroll
            for (int j = 0; j < 8; j++) {
                uint2 bh = B2h[(j * 4 + kk) * 32];
                uint2 bl = B2l[(j * 4 + kk) * 32];
                mma_bf16(&outv[4*j], a_h, bh.x, bh.y);
                mma_bf16(&outv[4*j], a_l, bh.x, bh.y);
                mma_bf16(&outv[4*j], a_h, bl.x, bl.y);
            }
        }

        // ---- store value tile (all rows valid: 56512 = 883*64) ----
        size_t tofs = (size_t)t * (NN * DD);
        float* pA = outA + tofs;
        float* pB = outB + tofs;
#pragma unroll
        for (int j = 0; j < 8; j++) {
            *reinterpret_cast<float2*>(pA + 8 * j) = make_float2(outv[4*j],   outv[4*j+1]);
            *reinterpret_cast<float2*>(pB + 8 * j) = make_float2(outv[4*j+2], outv[4*j+3]);
        }
    }
}

// ============================ launch =======================================
extern "C" void kernel_launch(void* const* d_in, const int* in_sizes, int n_in,
                              void* d_out, int out_size) {
    const float* x  = (const float*)d_in[0];
    const float* Mw = (const float*)d_in[1];
    float* out = (float*)d_out;

    ma_tables<<<192, 256>>>(Mw);
    ma_main<<<883, 128>>>(x, out);
}

// round 9
// speedup vs baseline: 1.8573x; 1.8573x over previous
#include <cuda_runtime.h>
#include <cuda_bf16.h>
#include <cstdint>

// ============================ problem constants ============================
#define BB   64
#define LL   12
#define NN   883
#define DD   64
#define TT   12
#define MM   64
#define ROWS  (BB*NN)           // 56512 = 883*64 exactly
#define TILES (ROWS/16)         // 3532 row-tiles of 16

// ============================ scratch ======================================
// A fragments (xs = sum_l x), fragment-major:
//   g_Ah/g_Al[(tile*4 + kk)*32 + lane] = uint4{ (rA,o), (rB,o), (rA,o+4), (rB,o+4) }
//   where rA = tile*16 + lane/4, rB = rA+8, o = 8*kk + lane%4 (u32 word = 2 packed bf16)
__device__ uint4 g_Ah[TILES * 4 * 32];
__device__ uint4 g_Al[TILES * 4 * 32];
// B fragments for mma.m16n8k16 (row.col), hi/lo interleaved per word:
//   g_B1/g_B2[((t*8 + j)*4 + kk)*32 + lane] = uint4{ hi.x, hi.y, lo.x, lo.y }
//   .x=pack(e_k,e_k+1), .y=pack(e_k+8,e_k+9) for n=8j+lane/4, k=16kk+2*(lane%4)
// GEMM1: B[k=d][n=m] = M[t][m][d]   GEMM2: B[k=m][n=d] = M[t][m][d]
__device__ uint4 g_B1[TT * 8 * 4 * 32];
__device__ uint4 g_B2[TT * 8 * 4 * 32];

// ============================ helpers ======================================
__device__ __forceinline__ uint32_t pack_bf16(__nv_bfloat16 lo, __nv_bfloat16 hi) {
    return (uint32_t)__bfloat16_as_ushort(lo) | ((uint32_t)__bfloat16_as_ushort(hi) << 16);
}
__device__ __forceinline__ void split_bf16(float v, __nv_bfloat16& h, __nv_bfloat16& l) {
    h = __float2bfloat16_rn(v);
    l = __float2bfloat16_rn(v - __bfloat162float(h));
}
// D += A * B  (m16n8k16, bf16 in, fp32 accum)
__device__ __forceinline__ void mma_bf16(float* c, const uint32_t* a,
                                         uint32_t b0, uint32_t b1) {
    asm volatile(
        "mma.sync.aligned.m16n8k16.row.col.f32.bf16.bf16.f32 "
        "{%0,%1,%2,%3}, {%4,%5,%6,%7}, {%8,%9}, {%0,%1,%2,%3};"
        : "+f"(c[0]), "+f"(c[1]), "+f"(c[2]), "+f"(c[3])
        : "r"(a[0]), "r"(a[1]), "r"(a[2]), "r"(a[3]), "r"(b0), "r"(b1));
}

// ========= kernel 1: reduce x over L, emit fragment-major xs splits ========
// one block per 16-row tile; 256 threads
__global__ __launch_bounds__(256) void ma_prep(const float* __restrict__ x) {
    __shared__ uint32_t sh_hi[16 * 32];
    __shared__ uint32_t sh_lo[16 * 32];
    int tid  = threadIdx.x;
    int tile = blockIdx.x;

    // phase 1: 16 threads per row, 4 d's per thread
    {
        int rl  = tid >> 4;
        int d4  = (tid & 15) * 4;
        int row = tile * 16 + rl;
        int b = row / NN;
        int n = row - b * NN;
        const float* base = x + ((size_t)b * LL * NN + n) * DD + d4;
        float4 acc = *reinterpret_cast<const float4*>(base);
#pragma unroll
        for (int l = 1; l < LL; l++) {
            float4 v = *reinterpret_cast<const float4*>(base + (size_t)l * NN * DD);
            acc.x += v.x; acc.y += v.y; acc.z += v.z; acc.w += v.w;
        }
        __nv_bfloat16 h0,l0,h1,l1,h2,l2,h3,l3;
        split_bf16(acc.x, h0, l0); split_bf16(acc.y, h1, l1);
        split_bf16(acc.z, h2, l2); split_bf16(acc.w, h3, l3);
        int w = rl * 32 + (d4 >> 1);
        sh_hi[w]     = pack_bf16(h0, h1);
        sh_hi[w + 1] = pack_bf16(h2, h3);
        sh_lo[w]     = pack_bf16(l0, l1);
        sh_lo[w + 1] = pack_bf16(l2, l3);
    }
    __syncthreads();

    // phase 2: 128 threads gather fragments, store uint4 lane-contiguous
    if (tid < 128) {
        int kk   = tid >> 5;
        int lane = tid & 31;
        int qr = lane >> 2, qc = lane & 3;
        int o  = 8 * kk + qc;
        int wA = qr * 32, wB = (qr + 8) * 32;
        uint4 vh = make_uint4(sh_hi[wA + o], sh_hi[wB + o],
                              sh_hi[wA + o + 4], sh_hi[wB + o + 4]);
        uint4 vl = make_uint4(sh_lo[wA + o], sh_lo[wB + o],
                              sh_lo[wA + o + 4], sh_lo[wB + o + 4]);
        int idx = (tile * 4 + kk) * 32 + lane;
        g_Ah[idx] = vh;
        g_Al[idx] = vl;
    }
}

// ================= kernel 2: build lane-indexed B fragment tables ==========
// one thread per uint4: 12t * 2g * 8j * 4kk * 32lane = 24576 -> 96 blocks x 256
__global__ __launch_bounds__(256) void ma_tables(const float* __restrict__ Mw) {
    int i = blockIdx.x * 256 + threadIdx.x;
    int lane =  i        & 31;
    int kk   = (i >> 5)  & 3;
    int j    = (i >> 7)  & 7;
    int g    = (i >> 10) & 1;
    int t    =  i >> 11;
    int nidx  = 8 * j + (lane >> 2);
    int kbase = 16 * kk + 2 * (lane & 3);
    const float* Mt = Mw + t * (MM * DD);
    float e0, e1, e2, e3;
    if (g == 0) {   // GEMM1: B[k=d][n=m] = M[m][d]
        int m = nidx;
        e0 = Mt[m * DD + kbase];
        e1 = Mt[m * DD + kbase + 1];
        e2 = Mt[m * DD + kbase + 8];
        e3 = Mt[m * DD + kbase + 9];
    } else {        // GEMM2: B[k=m][n=d] = M[m][d]
        int d = nidx;
        e0 = Mt[(kbase    ) * DD + d];
        e1 = Mt[(kbase + 1) * DD + d];
        e2 = Mt[(kbase + 8) * DD + d];
        e3 = Mt[(kbase + 9) * DD + d];
    }
    __nv_bfloat16 h0,l0,h1,l1,h2,l2,h3,l3;
    split_bf16(e0, h0, l0); split_bf16(e1, h1, l1);
    split_bf16(e2, h2, l2); split_bf16(e3, h3, l3);
    uint4 w = make_uint4(pack_bf16(h0, h1), pack_bf16(h2, h3),
                         pack_bf16(l0, l1), pack_bf16(l2, l3));
    int idx = ((t * 8 + j) * 4 + kk) * 32 + lane;
    if (g == 0) g_B1[idx] = w; else g_B2[idx] = w;
}

// ============== kernel 3: GEMM-softmax-GEMM (HMMA, low-reg) ================
// 128 threads = 4 warps; warp w owns tile blk*4+w (16 rows). 883 blocks.
__global__ __launch_bounds__(128, 4) void ma_main(float* __restrict__ out) {
    int tid  = threadIdx.x;
    int wid  = tid >> 5;
    int lane = tid & 31;
    int qr   = lane >> 2;
    int qc   = lane & 3;

    int tile = blockIdx.x * 4 + wid;
    int rA = tile * 16 + qr;
    int rB = rA + 8;
    int bA = rA / NN, nA = rA - bA * NN;
    int bB = rB / NN, nB = rB - bB * NN;
    float* outA = out + ((size_t)bA * TT * NN + nA) * DD + 2 * qc;
    float* outB = out + ((size_t)bB * TT * NN + nB) * DD + 2 * qc;

    const uint4* Ah = g_Ah + (size_t)tile * 4 * 32 + lane;
    const uint4* Al = g_Al + (size_t)tile * 4 * 32 + lane;
    const uint4* B1 = g_B1 + lane;
    const uint4* B2 = g_B2 + lane;

#pragma unroll 1
    for (int t = 0; t < TT; t++) {
        const uint4* b1t = B1 + (size_t)t * 1024;
        const uint4* b2t = B2 + (size_t)t * 1024;

        // ---- GEMM1: scores = xs @ M^T (3-term split; A and B per-kk loads) ----
        float acc[32];
#pragma unroll
        for (int i = 0; i < 32; i++) acc[i] = 0.f;
#pragma unroll
        for (int kk = 0; kk < 4; kk++) {
            uint4 a_h = Ah[kk * 32];
            uint4 a_l = Al[kk * 32];
            const uint32_t* ph = reinterpret_cast<const uint32_t*>(&a_h);
            const uint32_t* pl = reinterpret_cast<const uint32_t*>(&a_l);
#pragma unroll
            for (int j = 0; j < 8; j++) {
                uint4 b = b1t[(j * 4 + kk) * 32];
                mma_bf16(&acc[4*j], ph, b.x, b.y);
                mma_bf16(&acc[4*j], pl, b.x, b.y);
                mma_bf16(&acc[4*j], ph, b.z, b.w);
            }
        }

        // ---- softmax over 64 m (rows A/B split across 4-lane quads) ----
        float mA = -1e30f, mB = -1e30f;
#pragma unroll
        for (int j = 0; j < 8; j++) {
            mA = fmaxf(mA, fmaxf(acc[4*j],   acc[4*j+1]));
            mB = fmaxf(mB, fmaxf(acc[4*j+2], acc[4*j+3]));
        }
        mA = fmaxf(mA, __shfl_xor_sync(0xffffffffu, mA, 1));
        mA = fmaxf(mA, __shfl_xor_sync(0xffffffffu, mA, 2));
        mB = fmaxf(mB, __shfl_xor_sync(0xffffffffu, mB, 1));
        mB = fmaxf(mB, __shfl_xor_sync(0xffffffffu, mB, 2));
        float sA = 0.f, sB = 0.f;
#pragma unroll
        for (int j = 0; j < 8; j++) {
            acc[4*j]   = __expf(acc[4*j]   - mA);
            acc[4*j+1] = __expf(acc[4*j+1] - mA);
            acc[4*j+2] = __expf(acc[4*j+2] - mB);
            acc[4*j+3] = __expf(acc[4*j+3] - mB);
            sA += acc[4*j] + acc[4*j+1];
            sB += acc[4*j+2] + acc[4*j+3];
        }
        sA += __shfl_xor_sync(0xffffffffu, sA, 1);
        sA += __shfl_xor_sync(0xffffffffu, sA, 2);
        sB += __shfl_xor_sync(0xffffffffu, sB, 1);
        sB += __shfl_xor_sync(0xffffffffu, sB, 2);
        float iA = 1.0f / sA, iB = 1.0f / sB;

        // ---- GEMM2: value = p @ M (p split per kk; acc drains as outv fills) ----
        float outv[32];
#pragma unroll
        for (int i = 0; i < 32; i++) outv[i] = 0.f;
#pragma unroll
        for (int kk = 0; kk < 4; kk++) {
            int j0 = 2 * kk, j1 = 2 * kk + 1;
            uint32_t a_h[4], a_l[4];
            {
                __nv_bfloat16 h0,l0,h1,l1;
                split_bf16(acc[4*j0]   * iA, h0, l0);
                split_bf16(acc[4*j0+1] * iA, h1, l1);
                a_h[0] = pack_bf16(h0, h1); a_l[0] = pack_bf16(l0, l1);
                split_bf16(acc[4*j0+2] * iB, h0, l0);
                split_bf16(acc[4*j0+3] * iB, h1, l1);
                a_h[1] = pack_bf16(h0, h1); a_l[1] = pack_bf16(l0, l1);
                split_bf16(acc[4*j1]   * iA, h0, l0);
                split_bf16(acc[4*j1+1] * iA, h1, l1);
                a_h[2] = pack_bf16(h0, h1); a_l[2] = pack_bf16(l0, l1);
                split_bf16(acc[4*j1+2] * iB, h0, l0);
                split_bf16(acc[4*j1+3] * iB, h1, l1);
                a_h[3] = pack_bf16(h0, h1); a_l[3] = pack_bf16(l0, l1);
            }
#pragma unroll
            for (int j = 0; j < 8; j++) {
                uint4 b = b2t[(j * 4 + kk) * 32];
                mma_bf16(&outv[4*j], a_h, b.x, b.y);
                mma_bf16(&outv[4*j], a_l, b.x, b.y);
                mma_bf16(&outv[4*j], a_h, b.z, b.w);
            }
        }

        // ---- store value tile (all rows valid: 56512 = 883*64) ----
        size_t tofs = (size_t)t * (NN * DD);
        float* pA = outA + tofs;
        float* pB = outB + tofs;
#pragma unroll
        for (int j = 0; j < 8; j++) {
            *reinterpret_cast<float2*>(pA + 8 * j) = make_float2(outv[4*j],   outv[4*j+1]);
            *reinterpret_cast<float2*>(pB + 8 * j) = make_float2(outv[4*j+2], outv[4*j+3]);
        }
    }
}

// ============================ launch =======================================
extern "C" void kernel_launch(void* const* d_in, const int* in_sizes, int n_in,
                              void* d_out, int out_size) {
    const float* x  = (const float*)d_in[0];
    const float* Mw = (const float*)d_in[1];
    float* out = (float*)d_out;

    ma_tables<<<96, 256>>>(Mw);
    ma_prep<<<TILES, 256>>>(x);
    ma_main<<<883, 128>>>(out);
}

// round 10
// speedup vs baseline: 2.0184x; 1.0868x over previous
#include <cuda_runtime.h>
#include <cuda_bf16.h>
#include <cstdint>

// ============================ problem constants ============================
#define BB   64
#define LL   12
#define NN   883
#define DD   64
#define TT   12
#define MM   64
#define ROWS  (BB*NN)           // 56512 = 883*64 exactly
#define TILES (ROWS/16)         // 3532 row-tiles of 16

// ============================ scratch ======================================
// A fragments (xs = sum_l x), fragment-major:
//   g_Ah/g_Al[(tile*4 + kk)*32 + lane] = uint4{ (rA,o), (rB,o), (rA,o+4), (rB,o+4) }
//   rA = tile*16 + lane/4, rB = rA+8, o = 8*kk + lane%4 (u32 word = 2 packed bf16)
__device__ uint4 g_Ah[TILES * 4 * 32];
__device__ uint4 g_Al[TILES * 4 * 32];
// B fragments for mma.m16n8k16 (row.col), hi/lo interleaved per uint4:
//   g_B1/g_B2[((t*8 + j)*4 + kk)*32 + lane] = { hi.x, hi.y, lo.x, lo.y }
// GEMM1: B[k=d][n=m] = M[t][m][d]   GEMM2: B[k=m][n=d] = M[t][m][d]
__device__ uint4 g_B1[TT * 8 * 4 * 32];
__device__ uint4 g_B2[TT * 8 * 4 * 32];

// ============================ helpers ======================================
__device__ __forceinline__ uint32_t pack_bf16(__nv_bfloat16 lo, __nv_bfloat16 hi) {
    return (uint32_t)__bfloat16_as_ushort(lo) | ((uint32_t)__bfloat16_as_ushort(hi) << 16);
}
__device__ __forceinline__ void split_bf16(float v, __nv_bfloat16& h, __nv_bfloat16& l) {
    h = __float2bfloat16_rn(v);
    l = __float2bfloat16_rn(v - __bfloat162float(h));
}
__device__ __forceinline__ uint32_t smem_u32(const void* p) {
    uint32_t a;
    asm("{ .reg .u64 t; cvta.to.shared.u64 t, %1; cvt.u32.u64 %0, t; }" : "=r"(a) : "l"(p));
    return a;
}
// D += A * B  (m16n8k16, bf16 in, fp32 accum)
__device__ __forceinline__ void mma_bf16(float* c, const uint32_t* a,
                                         uint32_t b0, uint32_t b1) {
    asm volatile(
        "mma.sync.aligned.m16n8k16.row.col.f32.bf16.bf16.f32 "
        "{%0,%1,%2,%3}, {%4,%5,%6,%7}, {%8,%9}, {%0,%1,%2,%3};"
        : "+f"(c[0]), "+f"(c[1]), "+f"(c[2]), "+f"(c[3])
        : "r"(a[0]), "r"(a[1]), "r"(a[2]), "r"(a[3]), "r"(b0), "r"(b1));
}
#define CP_COMMIT() asm volatile("cp.async.commit_group;" ::: "memory")
#define CP_WAIT(n)  asm volatile("cp.async.wait_group %0;" :: "n"(n) : "memory")

// ===== kernel 1: reduce x over L -> A fragments; build B tables (merged) ===
__global__ __launch_bounds__(256) void ma_prep(const float* __restrict__ x,
                                               const float* __restrict__ Mw) {
    if (blockIdx.x < (unsigned)TILES) {
        __shared__ uint32_t sh_hi[16 * 32];
        __shared__ uint32_t sh_lo[16 * 32];
        int tid  = threadIdx.x;
        int tile = blockIdx.x;
        // phase 1: 16 threads per row, 4 d's per thread
        {
            int rl  = tid >> 4;
            int d4  = (tid & 15) * 4;
            int row = tile * 16 + rl;
            int b = row / NN;
            int n = row - b * NN;
            const float* base = x + ((size_t)b * LL * NN + n) * DD + d4;
            float4 acc = *reinterpret_cast<const float4*>(base);
#pragma unroll
            for (int l = 1; l < LL; l++) {
                float4 v = *reinterpret_cast<const float4*>(base + (size_t)l * NN * DD);
                acc.x += v.x; acc.y += v.y; acc.z += v.z; acc.w += v.w;
            }
            __nv_bfloat16 h0,l0,h1,l1,h2,l2,h3,l3;
            split_bf16(acc.x, h0, l0); split_bf16(acc.y, h1, l1);
            split_bf16(acc.z, h2, l2); split_bf16(acc.w, h3, l3);
            int w = rl * 32 + (d4 >> 1);
            sh_hi[w]     = pack_bf16(h0, h1);
            sh_hi[w + 1] = pack_bf16(h2, h3);
            sh_lo[w]     = pack_bf16(l0, l1);
            sh_lo[w + 1] = pack_bf16(l2, l3);
        }
        __syncthreads();
        // phase 2: 128 threads gather fragments, store uint4 lane-contiguous
        if (tid < 128) {
            int kk   = tid >> 5;
            int lane = tid & 31;
            int qr = lane >> 2, qc = lane & 3;
            int o  = 8 * kk + qc;
            int wA = qr * 32, wB = (qr + 8) * 32;
            uint4 vh = make_uint4(sh_hi[wA + o], sh_hi[wB + o],
                                  sh_hi[wA + o + 4], sh_hi[wB + o + 4]);
            uint4 vl = make_uint4(sh_lo[wA + o], sh_lo[wB + o],
                                  sh_lo[wA + o + 4], sh_lo[wB + o + 4]);
            int idx = (tile * 4 + kk) * 32 + lane;
            g_Ah[idx] = vh;
            g_Al[idx] = vl;
        }
    } else {
        // B tables: one thread per uint4 (12t * 2g * 8j * 4kk * 32lane = 24576)
        int i = (blockIdx.x - TILES) * 256 + threadIdx.x;
        int lane =  i        & 31;
        int kk   = (i >> 5)  & 3;
        int j    = (i >> 7)  & 7;
        int g    = (i >> 10) & 1;
        int t    =  i >> 11;
        int nidx  = 8 * j + (lane >> 2);
        int kbase = 16 * kk + 2 * (lane & 3);
        const float* Mt = Mw + t * (MM * DD);
        float e0, e1, e2, e3;
        if (g == 0) {   // GEMM1: B[k=d][n=m] = M[m][d]
            int m = nidx;
            e0 = Mt[m * DD + kbase];
            e1 = Mt[m * DD + kbase + 1];
            e2 = Mt[m * DD + kbase + 8];
            e3 = Mt[m * DD + kbase + 9];
        } else {        // GEMM2: B[k=m][n=d] = M[m][d]
            int d = nidx;
            e0 = Mt[(kbase    ) * DD + d];
            e1 = Mt[(kbase + 1) * DD + d];
            e2 = Mt[(kbase + 8) * DD + d];
            e3 = Mt[(kbase + 9) * DD + d];
        }
        __nv_bfloat16 h0,l0,h1,l1,h2,l2,h3,l3;
        split_bf16(e0, h0, l0); split_bf16(e1, h1, l1);
        split_bf16(e2, h2, l2); split_bf16(e3, h3, l3);
        uint4 w = make_uint4(pack_bf16(h0, h1), pack_bf16(h2, h3),
                             pack_bf16(l0, l1), pack_bf16(l2, l3));
        int idx = ((t * 8 + j) * 4 + kk) * 32 + lane;
        if (g == 0) g_B1[idx] = w; else g_B2[idx] = w;
    }
}

// ======= kernel 2: GEMM-softmax-GEMM, B staged in smem via cp.async ========
// 128 threads = 4 warps; warp w owns tile blk*4+w (16 rows). 883 blocks.
// Phase p = 2t (B1[t] -> slot0) or 2t+1 (B2[t] -> slot1). Double-buffered.
__global__ __launch_bounds__(128) void ma_main(float* __restrict__ out) {
    __shared__ uint4 sbuf[2][1024];   // [slot][ (j*4+kk)*32 + lane ] = 32 KB

    int tid  = threadIdx.x;
    int wid  = tid >> 5;
    int lane = tid & 31;
    int qr   = lane >> 2;
    int qc   = lane & 3;

    const uint32_t sb = smem_u32(sbuf);

    // async copy of phase p's 16 KB table into its slot (8 x 16B per thread)
    auto cp_phase = [&](int p) {
        if (p < 2 * TT) {
            int t = p >> 1;
            const uint4* src = ((p & 1) ? g_B2 : g_B1) + (size_t)t * 1024 + tid;
            uint32_t dst = sb + ((uint32_t)(p & 1) * 1024 + tid) * 16;
#pragma unroll
            for (int k = 0; k < 8; k++)
                asm volatile("cp.async.cg.shared.global [%0], [%1], 16;"
                             :: "r"(dst + k * 2048), "l"(src + k * 128) : "memory");
        }
    };

    int tile = blockIdx.x * 4 + wid;
    int rA = tile * 16 + qr;
    int rB = rA + 8;
    int bA = rA / NN, nA = rA - bA * NN;
    int bB = rB / NN, nB = rB - bB * NN;
    float* outA = out + ((size_t)bA * TT * NN + nA) * DD + 2 * qc;
    float* outB = out + ((size_t)bB * TT * NN + nB) * DD + 2 * qc;

    const uint4* Ah = g_Ah + (size_t)tile * 4 * 32 + lane;
    const uint4* Al = g_Al + (size_t)tile * 4 * 32 + lane;
    const uint4* S0 = &sbuf[0][lane];
    const uint4* S1 = &sbuf[1][lane];

    // prologue: start loading phase 0 (B1[0])
    cp_phase(0);
    CP_COMMIT();

#pragma unroll 1
    for (int t = 0; t < TT; t++) {
        // ================= phase 2t: GEMM1 (slot 0) =================
        __syncthreads();                 // slot1 free (prev GEMM2 done)
        cp_phase(2 * t + 1);
        CP_COMMIT();
        CP_WAIT(1);                      // phase 2t resident
        __syncthreads();

        float acc[32];
#pragma unroll
        for (int i = 0; i < 32; i++) acc[i] = 0.f;
#pragma unroll
        for (int kk = 0; kk < 4; kk++) {
            uint4 a_h = Ah[kk * 32];
            uint4 a_l = Al[kk * 32];
            const uint32_t* ph = reinterpret_cast<const uint32_t*>(&a_h);
            const uint32_t* pl = reinterpret_cast<const uint32_t*>(&a_l);
#pragma unroll
            for (int j = 0; j < 8; j++) {
                uint4 b = S0[(j * 4 + kk) * 32];
                mma_bf16(&acc[4*j], ph, b.x, b.y);
                mma_bf16(&acc[4*j], pl, b.x, b.y);
                mma_bf16(&acc[4*j], ph, b.z, b.w);
            }
        }

        // ---- softmax over 64 m ----
        float mA = -1e30f, mB = -1e30f;
#pragma unroll
        for (int j = 0; j < 8; j++) {
            mA = fmaxf(mA, fmaxf(acc[4*j],   acc[4*j+1]));
            mB = fmaxf(mB, fmaxf(acc[4*j+2], acc[4*j+3]));
        }
        mA = fmaxf(mA, __shfl_xor_sync(0xffffffffu, mA, 1));
        mA = fmaxf(mA, __shfl_xor_sync(0xffffffffu, mA, 2));
        mB = fmaxf(mB, __shfl_xor_sync(0xffffffffu, mB, 1));
        mB = fmaxf(mB, __shfl_xor_sync(0xffffffffu, mB, 2));
        float sA = 0.f, sB = 0.f;
#pragma unroll
        for (int j = 0; j < 8; j++) {
            acc[4*j]   = __expf(acc[4*j]   - mA);
            acc[4*j+1] = __expf(acc[4*j+1] - mA);
            acc[4*j+2] = __expf(acc[4*j+2] - mB);
            acc[4*j+3] = __expf(acc[4*j+3] - mB);
            sA += acc[4*j] + acc[4*j+1];
            sB += acc[4*j+2] + acc[4*j+3];
        }
        sA += __shfl_xor_sync(0xffffffffu, sA, 1);
        sA += __shfl_xor_sync(0xffffffffu, sA, 2);
        sB += __shfl_xor_sync(0xffffffffu, sB, 1);
        sB += __shfl_xor_sync(0xffffffffu, sB, 2);
        float iA = 1.0f / sA, iB = 1.0f / sB;

        // ================= phase 2t+1: GEMM2 (slot 1) =================
        __syncthreads();                 // slot0 free (GEMM1 above done)
        cp_phase(2 * t + 2);
        if (t < TT - 1) { CP_COMMIT(); CP_WAIT(1); }
        else            { CP_WAIT(0); }
        __syncthreads();

        float outv[32];
#pragma unroll
        for (int i = 0; i < 32; i++) outv[i] = 0.f;
#pragma unroll
        for (int kk = 0; kk < 4; kk++) {
            int j0 = 2 * kk, j1 = 2 * kk + 1;
            uint32_t a_h[4], a_l[4];
            {
                __nv_bfloat16 h0,l0,h1,l1;
                split_bf16(acc[4*j0]   * iA, h0, l0);
                split_bf16(acc[4*j0+1] * iA, h1, l1);
                a_h[0] = pack_bf16(h0, h1); a_l[0] = pack_bf16(l0, l1);
                split_bf16(acc[4*j0+2] * iB, h0, l0);
                split_bf16(acc[4*j0+3] * iB, h1, l1);
                a_h[1] = pack_bf16(h0, h1); a_l[1] = pack_bf16(l0, l1);
                split_bf16(acc[4*j1]   * iA, h0, l0);
                split_bf16(acc[4*j1+1] * iA, h1, l1);
                a_h[2] = pack_bf16(h0, h1); a_l[2] = pack_bf16(l0, l1);
                split_bf16(acc[4*j1+2] * iB, h0, l0);
                split_bf16(acc[4*j1+3] * iB, h1, l1);
                a_h[3] = pack_bf16(h0, h1); a_l[3] = pack_bf16(l0, l1);
            }
#pragma unroll
            for (int j = 0; j < 8; j++) {
                uint4 b = S1[(j * 4 + kk) * 32];
                mma_bf16(&outv[4*j], a_h, b.x, b.y);
                mma_bf16(&outv[4*j], a_l, b.x, b.y);
                mma_bf16(&outv[4*j], a_h, b.z, b.w);
            }
        }

        // ---- store value tile (all rows valid: 56512 = 883*64) ----
        size_t tofs = (size_t)t * (NN * DD);
        float* pA = outA + tofs;
        float* pB = outB + tofs;
#pragma unroll
        for (int j = 0; j < 8; j++) {
            *reinterpret_cast<float2*>(pA + 8 * j) = make_float2(outv[4*j],   outv[4*j+1]);
            *reinterpret_cast<float2*>(pB + 8 * j) = make_float2(outv[4*j+2], outv[4*j+3]);
        }
    }
}

// ============================ launch =======================================
extern "C" void kernel_launch(void* const* d_in, const int* in_sizes, int n_in,
                              void* d_out, int out_size) {
    const float* x  = (const float*)d_in[0];
    const float* Mw = (const float*)d_in[1];
    float* out = (float*)d_out;

    ma_prep<<<TILES + 96, 256>>>(x, Mw);
    ma_main<<<883, 128>>>(out);
}